// round 7
// baseline (speedup 1.0000x reference)
#include <cuda_runtime.h>
#include <cstdint>

// VectorQuantizer: x [32,2048,64] f32, codebook [1024,64] f32
// out f32: quantized [32,64,2048] | loss | indices [32,2048]

#define N_TOK   (32 * 2048)
#define K_CODES 1024
#define D_DIM   64
#define T_LEN   2048
#define LOSS_OFF ((size_t)N_TOK * D_DIM)
#define IDX_OFF  (LOSS_OFF + 1)
#define DELTA    1e-3f
#define SE_SCALE ((1.0f / 1024.0f) / 127.0f)    // fixed e quant scale (|e| < 1/1024)

#define BDIM    128
#define CHUNK   128
#define NCH     (K_CODES / CHUNK)               // 8

__device__ double g_loss_acc;
__device__ float  g_bsq[K_CODES];
__device__ int    g_flag_cnt;
__device__ int    g_flags[N_TOK];
__device__ float  g_ns2[N_TOK];                  // -2 * sx * se per token
__device__ uint32_t g_qx[(size_t)N_TOK * 16];    // int8 x, 16 u32 per token
__device__ uint32_t g_qe[K_CODES * 16];          // int8 e, 16 u32 per code

#define CP_ASYNC16(dst, src) \
    asm volatile("cp.async.cg.shared.global [%0], [%1], 16;" \
        :: "r"(dst), "l"(__cvta_generic_to_global(src)) : "memory")
#define CP_COMMIT() asm volatile("cp.async.commit_group;" ::: "memory")
#define CP_WAIT1()  asm volatile("cp.async.wait_group 1;" ::: "memory")

__device__ __forceinline__ uint32_t smem_u32(const void* p) {
    uint32_t a;
    asm("{ .reg .u64 t; cvta.to.shared.u64 t, %1; cvt.u32.u64 %0, t; }" : "=r"(a) : "l"(p));
    return a;
}

// ---------------- prep kernels ----------------
// bsq (reference-exact sequential rounding) + global init
__global__ void vq_bsq_init_kernel(const float* __restrict__ cb) {
    int k = blockIdx.x * blockDim.x + threadIdx.x;
    if (k == 0) { g_loss_acc = 0.0; g_flag_cnt = 0; }
    if (k >= K_CODES) return;
    float s = 0.0f;
    const float* row = cb + (size_t)k * D_DIM;
    #pragma unroll 8
    for (int i = 0; i < D_DIM; i++) s = __fadd_rn(s, __fmul_rn(row[i], row[i]));
    g_bsq[k] = s;
}

__device__ __forceinline__ uint32_t pack4(float a, float b, float c, float d, float inv) {
    int i0 = __float2int_rn(a * inv), i1 = __float2int_rn(b * inv);
    int i2 = __float2int_rn(c * inv), i3 = __float2int_rn(d * inv);
    return (uint32_t)(i0 & 0xff) | ((uint32_t)(i1 & 0xff) << 8) |
           ((uint32_t)(i2 & 0xff) << 16) | ((uint32_t)(i3 & 0xff) << 24);
}

// per-token int8 quantization of x (scale = gmax/127)
__global__ void vq_quant_x_kernel(const float* __restrict__ x) {
    int tok = blockIdx.x * blockDim.x + threadIdx.x;
    const float4* xr = (const float4*)(x + (size_t)tok * D_DIM);
    float4 v[16];
    float gmax = 0.0f;
    #pragma unroll
    for (int j = 0; j < 16; j++) {
        v[j] = xr[j];
        gmax = fmaxf(gmax, fmaxf(fmaxf(fabsf(v[j].x), fabsf(v[j].y)),
                                 fmaxf(fabsf(v[j].z), fabsf(v[j].w))));
    }
    gmax = fmaxf(gmax, 1e-20f);
    float inv = 127.0f / gmax;
    float sx  = gmax / 127.0f;
    #pragma unroll
    for (int j = 0; j < 16; j++)
        g_qx[(size_t)tok * 16 + j] = pack4(v[j].x, v[j].y, v[j].z, v[j].w, inv);
    g_ns2[tok] = -2.0f * sx * SE_SCALE;
}

// fixed-scale int8 quantization of codebook
__global__ void vq_quant_e_kernel(const float* __restrict__ cb) {
    int i = blockIdx.x * blockDim.x + threadIdx.x;   // one u32 (4 elems)
    const float4 v = ((const float4*)cb)[i];
    g_qe[i] = pack4(v.x, v.y, v.z, v.w, 1.0f / SE_SCALE);
}

// ---------------- dp4a screen kernel ----------------
__global__ __launch_bounds__(BDIM) void vq_screen_kernel(
    const float* __restrict__ x, const float* __restrict__ cb, float* __restrict__ out)
{
    __shared__ uint32_t sE[2][CHUNK * 16];   // int8 codes: 8KB per buffer
    __shared__ float    sB[2][CHUNK];
    __shared__ int      s_idx[BDIM];

    const int tid  = threadIdx.x;
    const int tok  = blockIdx.x * BDIM + tid;
    const uint32_t sEb0 = smem_u32(&sE[0][0]);
    const uint32_t sEb1 = smem_u32(&sE[1][0]);
    const uint32_t sBb0 = smem_u32(&sB[0][0]);
    const uint32_t sBb1 = smem_u32(&sB[1][0]);

    // resident x (int8 packed: 16 regs)
    uint32_t xq[16];
    #pragma unroll
    for (int j = 0; j < 16; j++) xq[j] = g_qx[(size_t)tok * 16 + j];
    const float ns2 = g_ns2[tok];

    // prologue: chunks 0 and 1
    #pragma unroll
    for (int cc = 0; cc < 2; cc++) {
        uint32_t eb = cc ? sEb1 : sEb0, bb = cc ? sBb1 : sBb0;
        #pragma unroll
        for (int u = 0; u < 4; u++)
            CP_ASYNC16(eb + (tid * 4 + u * BDIM * 4) * 4,
                       g_qe + cc * CHUNK * 16 + tid * 4 + u * BDIM * 4);
        if (tid < 32) CP_ASYNC16(bb + tid * 16, g_bsq + cc * CHUNK + tid * 4);
        CP_COMMIT();
    }

    float m1 = 3.402823466e38f, m2 = 3.402823466e38f;
    int   i1 = 0;

    for (int ch = 0; ch < NCH; ch++) {
        CP_WAIT1();
        __syncthreads();
        const int buf = ch & 1;
        const uint4* ep = (const uint4*)&sE[buf][0];
        const float* bp = &sB[buf][0];

        #pragma unroll 2
        for (int c = 0; c < CHUNK; c++) {
            uint4 e0 = ep[c * 4 + 0];
            uint4 e1 = ep[c * 4 + 1];
            uint4 e2 = ep[c * 4 + 2];
            uint4 e3 = ep[c * 4 + 3];
            int a0 = 0, a1 = 0, a2 = 0, a3 = 0;
            a0 = __dp4a((int)xq[0],  (int)e0.x, a0);
            a1 = __dp4a((int)xq[1],  (int)e0.y, a1);
            a2 = __dp4a((int)xq[2],  (int)e0.z, a2);
            a3 = __dp4a((int)xq[3],  (int)e0.w, a3);
            a0 = __dp4a((int)xq[4],  (int)e1.x, a0);
            a1 = __dp4a((int)xq[5],  (int)e1.y, a1);
            a2 = __dp4a((int)xq[6],  (int)e1.z, a2);
            a3 = __dp4a((int)xq[7],  (int)e1.w, a3);
            a0 = __dp4a((int)xq[8],  (int)e2.x, a0);
            a1 = __dp4a((int)xq[9],  (int)e2.y, a1);
            a2 = __dp4a((int)xq[10], (int)e2.z, a2);
            a3 = __dp4a((int)xq[11], (int)e2.w, a3);
            a0 = __dp4a((int)xq[12], (int)e3.x, a0);
            a1 = __dp4a((int)xq[13], (int)e3.y, a1);
            a2 = __dp4a((int)xq[14], (int)e3.z, a2);
            a3 = __dp4a((int)xq[15], (int)e3.w, a3);
            int idot = (a0 + a1) + (a2 + a3);
            float d = fmaf(ns2, (float)idot, bp[c]);
            if (d < m1) { m2 = m1; m1 = d; i1 = ch * CHUNK + c; }
            else if (d < m2) { m2 = d; }
        }

        __syncthreads();
        if (ch + 2 < NCH) {
            uint32_t eb = buf ? sEb1 : sEb0, bb = buf ? sBb1 : sBb0;
            #pragma unroll
            for (int u = 0; u < 4; u++)
                CP_ASYNC16(eb + (tid * 4 + u * BDIM * 4) * 4,
                           g_qe + (ch + 2) * CHUNK * 16 + tid * 4 + u * BDIM * 4);
            if (tid < 32) CP_ASYNC16(bb + tid * 16, g_bsq + (ch + 2) * CHUNK + tid * 4);
        }
        CP_COMMIT();   // always commit (possibly empty) to keep group count uniform
    }

    s_idx[tid] = (m2 - m1 < DELTA) ? -1 : i1;
    __syncthreads();

    // ---- epilogue (validated R5 pattern) ----
    const int myidx = s_idx[tid];
    double ls = 0.0;
    if (myidx < 0) {
        int pos = atomicAdd(&g_flag_cnt, 1);
        g_flags[pos] = tok;
    } else {
        const int bq = tok >> 11, tq = tok & 2047;
        float* qout = out + ((size_t)bq * D_DIM) * T_LEN + tq;
        const float* xr = x + (size_t)tok * D_DIM;
        const float* er = cb + (size_t)myidx * D_DIM;
        #pragma unroll
        for (int i = 0; i < D_DIM; i++) {
            float xv = xr[i];
            float dv = __fadd_rn(er[i], -xv);
            ls += (double)dv * dv;
            qout[(size_t)i * T_LEN] = __fadd_rn(xv, dv);
        }
        out[IDX_OFF + tok] = (float)myidx;
    }
    #pragma unroll
    for (int o = 16; o > 0; o >>= 1)
        ls += __shfl_down_sync(0xffffffffu, ls, o);
    if ((tid & 31) == 0 && ls != 0.0) atomicAdd(&g_loss_acc, ls);
}

// ---------------- exact repair kernel (R1-bitwise; validated in R5) ----------------
#define EX_GRID 512
__global__ __launch_bounds__(128) void vq_exact_kernel(
    const float* __restrict__ x, const float* __restrict__ cb, float* __restrict__ out)
{
    const int cnt = g_flag_cnt;
    if (blockIdx.x * 8 >= cnt) return;
    __shared__ float sx[8][D_DIM];
    __shared__ int   stok[8];
    const int g = threadIdx.x >> 4, c = threadIdx.x & 15;

    for (int base = blockIdx.x * 8; base < cnt; base += EX_GRID * 8) {
        __syncthreads();
        int slot = base + g;
        if (c == 0) stok[g] = (slot < cnt) ? g_flags[slot] : -1;
        __syncthreads();
        int tok = stok[g];
        if (tok >= 0) {
            #pragma unroll
            for (int i = 0; i < 4; i++) sx[g][c * 4 + i] = x[(size_t)tok * D_DIM + c * 4 + i];
        }
        __syncthreads();

        float best = 3.402823466e38f; int bidx = 0;
        if (tok >= 0) {
            float A = 0.0f;
            #pragma unroll
            for (int i = 0; i < D_DIM; i++) A = __fadd_rn(A, __fmul_rn(sx[g][i], sx[g][i]));
            for (int t = 0; t < K_CODES / 16; t++) {
                int k = c + 16 * t;
                const float* e = cb + (size_t)k * D_DIM;
                float a0 = 0.f, a1 = 0.f, a2 = 0.f, a3 = 0.f;
                #pragma unroll
                for (int j = 0; j < 16; j++) {
                    a0 = fmaf(sx[g][4 * j + 0], e[4 * j + 0], a0);
                    a1 = fmaf(sx[g][4 * j + 1], e[4 * j + 1], a1);
                    a2 = fmaf(sx[g][4 * j + 2], e[4 * j + 2], a2);
                    a3 = fmaf(sx[g][4 * j + 3], e[4 * j + 3], a3);
                }
                float dot = __fadd_rn(__fadd_rn(a0, a1), __fadd_rn(a2, a3));
                float tv  = __fadd_rn(A, g_bsq[k]);
                float d   = __fadd_rn(tv, -__fmul_rn(2.0f, dot));
                if (d < best) { best = d; bidx = k; }
            }
        }
        #pragma unroll
        for (int o = 8; o > 0; o >>= 1) {
            float ob = __shfl_down_sync(0xffffffffu, best, o, 16);
            int   oi = __shfl_down_sync(0xffffffffu, bidx, o, 16);
            if (ob < best || (ob == best && oi < bidx)) { best = ob; bidx = oi; }
        }
        if (tok >= 0 && c == 0) {
            const int bq = tok >> 11, tq = tok & 2047;
            float* qout = out + ((size_t)bq * D_DIM) * T_LEN + tq;
            const float* er = cb + (size_t)bidx * D_DIM;
            double ls = 0.0;
            #pragma unroll
            for (int i = 0; i < D_DIM; i++) {
                float xv = sx[g][i];
                float dv = __fadd_rn(er[i], -xv);
                ls += (double)dv * dv;
                qout[(size_t)i * T_LEN] = __fadd_rn(xv, dv);
            }
            out[IDX_OFF + tok] = (float)bidx;
            atomicAdd(&g_loss_acc, ls);
        }
    }
}

__global__ void vq_finalize_kernel(float* __restrict__ out) {
    double m = g_loss_acc / (double)((size_t)N_TOK * D_DIM);
    out[LOSS_OFF] = (float)(m + 0.25 * m);
}

extern "C" void kernel_launch(void* const* d_in, const int* in_sizes, int n_in,
                              void* d_out, int out_size) {
    const float* x  = (const float*)d_in[0];
    const float* cb = (const float*)d_in[1];
    float* out = (float*)d_out;
    (void)in_sizes; (void)n_in; (void)out_size;

    vq_bsq_init_kernel<<<8, 128>>>(cb);
    vq_quant_x_kernel<<<N_TOK / 256, 256>>>(x);
    vq_quant_e_kernel<<<(K_CODES * 16) / 256, 256>>>(cb);
    vq_screen_kernel<<<N_TOK / BDIM, BDIM>>>(x, cb, out);
    vq_exact_kernel<<<EX_GRID, 128>>>(x, cb, out);
    vq_finalize_kernel<<<1, 1>>>(out);
}

// round 9
// speedup vs baseline: 10.7843x; 10.7843x over previous
#include <cuda_runtime.h>
#include <cstdint>

// VectorQuantizer: x [32,2048,64] f32, codebook [1024,64] f32
// out f32: quantized [32,64,2048] | loss | indices [32,2048]

#define N_TOK   (32 * 2048)
#define K_CODES 1024
#define D_DIM   64
#define T_LEN   2048
#define LOSS_OFF ((size_t)N_TOK * D_DIM)
#define IDX_OFF  (LOSS_OFF + 1)
#define DELTA    1.5e-3f
#define SE_SCALE ((1.0f / 1024.0f) / 127.0f)    // fixed e quant scale (|e| < 1/1024)

#define BDIM    128
#define CHUNK   128
#define NCH     (K_CODES / CHUNK)               // 8

// dynamic smem layout (bytes)
#define SM_E0   0                                // 2048 u32 = 8192
#define SM_E1   8192
#define SM_B0   16384                            // 128 f32 = 512
#define SM_B1   16896
#define SM_X    17408                            // 128 x 65 f32 = 33280
#define SMEM_SZ 50688

__device__ double g_loss_acc;
__device__ float  g_bsq[K_CODES];
__device__ int    g_flag_cnt;
__device__ int    g_flags[N_TOK];
__device__ float  g_ns2[N_TOK];                  // -2 * sx * se per token
__device__ uint32_t g_qx[(size_t)N_TOK * 16];    // int8 x, 16 u32 per token
__device__ uint32_t g_qe[K_CODES * 16];          // int8 e, 16 u32 per code

#define CP_ASYNC16(dst, src) \
    asm volatile("cp.async.cg.shared.global [%0], [%1], 16;" \
        :: "r"(dst), "l"(__cvta_generic_to_global(src)) : "memory")
#define CP_COMMIT() asm volatile("cp.async.commit_group;" ::: "memory")
#define CP_WAIT1()  asm volatile("cp.async.wait_group 1;" ::: "memory")

__device__ __forceinline__ uint32_t smem_u32(const void* p) {
    uint32_t a;
    asm("{ .reg .u64 t; cvta.to.shared.u64 t, %1; cvt.u32.u64 %0, t; }" : "=r"(a) : "l"(p));
    return a;
}

// ---------------- prep kernels ----------------
__global__ void vq_bsq_init_kernel(const float* __restrict__ cb) {
    int k = blockIdx.x * blockDim.x + threadIdx.x;
    if (k == 0) { g_loss_acc = 0.0; g_flag_cnt = 0; }
    if (k >= K_CODES) return;
    float s = 0.0f;
    const float* row = cb + (size_t)k * D_DIM;
    #pragma unroll 8
    for (int i = 0; i < D_DIM; i++) s = __fadd_rn(s, __fmul_rn(row[i], row[i]));
    g_bsq[k] = s;
}

__device__ __forceinline__ uint32_t pack4(float a, float b, float c, float d, float inv) {
    int i0 = __float2int_rn(a * inv), i1 = __float2int_rn(b * inv);
    int i2 = __float2int_rn(c * inv), i3 = __float2int_rn(d * inv);
    return (uint32_t)(i0 & 0xff) | ((uint32_t)(i1 & 0xff) << 8) |
           ((uint32_t)(i2 & 0xff) << 16) | ((uint32_t)(i3 & 0xff) << 24);
}

__global__ void vq_quant_x_kernel(const float* __restrict__ x) {
    int tok = blockIdx.x * blockDim.x + threadIdx.x;
    const float4* xr = (const float4*)(x + (size_t)tok * D_DIM);
    float4 v[16];
    float gmax = 0.0f;
    #pragma unroll
    for (int j = 0; j < 16; j++) {
        v[j] = xr[j];
        gmax = fmaxf(gmax, fmaxf(fmaxf(fabsf(v[j].x), fabsf(v[j].y)),
                                 fmaxf(fabsf(v[j].z), fabsf(v[j].w))));
    }
    gmax = fmaxf(gmax, 1e-20f);
    float inv = 127.0f / gmax;
    float sx  = gmax / 127.0f;
    #pragma unroll
    for (int j = 0; j < 16; j++)
        g_qx[(size_t)tok * 16 + j] = pack4(v[j].x, v[j].y, v[j].z, v[j].w, inv);
    g_ns2[tok] = -2.0f * sx * SE_SCALE;
}

__global__ void vq_quant_e_kernel(const float* __restrict__ cb) {
    int i = blockIdx.x * blockDim.x + threadIdx.x;
    const float4 v = ((const float4*)cb)[i];
    g_qe[i] = pack4(v.x, v.y, v.z, v.w, 1.0f / SE_SCALE);
}

// ---------------- screen + in-kernel exact resolve ----------------
__global__ __launch_bounds__(BDIM) void vq_screen_kernel(
    const float* __restrict__ x, const float* __restrict__ cb, float* __restrict__ out)
{
    extern __shared__ char smem[];
    __shared__ float s_wl[4];
    const uint32_t sb = smem_u32(smem);
    const int tid = threadIdx.x;
    const int tok = blockIdx.x * BDIM + tid;
    const int blk0 = blockIdx.x * BDIM;

    // prologue: E chunks 0,1 + bsq slices via cp.async (two groups)
    #pragma unroll
    for (int cc = 0; cc < 2; cc++) {
        uint32_t eb = sb + (cc ? SM_E1 : SM_E0);
        uint32_t bb = sb + (cc ? SM_B1 : SM_B0);
        #pragma unroll
        for (int u = 0; u < 4; u++)
            CP_ASYNC16(eb + (tid * 4 + u * BDIM * 4) * 4,
                       g_qe + cc * CHUNK * 16 + tid * 4 + u * BDIM * 4);
        if (tid < 32) CP_ASYNC16(bb + tid * 16, g_bsq + cc * CHUNK + tid * 4);
        CP_COMMIT();
    }

    // stage x rows into padded smem (coalesced gmem reads)
    {
        float* sx = (float*)(smem + SM_X);
        #pragma unroll
        for (int u = tid; u < BDIM * D_DIM; u += BDIM) {
            int row = u >> 6, col = u & 63;
            sx[row * 65 + col] = x[(size_t)blk0 * D_DIM + u];
        }
    }

    // resident int8 x (vectorized load)
    uint32_t xq[16];
    {
        const uint4* qp = (const uint4*)(g_qx + (size_t)tok * 16);
        #pragma unroll
        for (int j = 0; j < 4; j++) {
            uint4 v = qp[j];
            xq[4 * j + 0] = v.x; xq[4 * j + 1] = v.y;
            xq[4 * j + 2] = v.z; xq[4 * j + 3] = v.w;
        }
    }
    const float ns2 = g_ns2[tok];

    // candidate ring (last 8 inserts) + running min
    float m1  = 3.402823466e38f;
    float lim = 3.402823466e38f;
    int   rk[8];
    float rf[8];
    #pragma unroll
    for (int j = 0; j < 8; j++) { rk[j] = 0; rf[j] = 3.402823466e38f; }
    int n_ins = 0, cnt_since = 0;

    for (int ch = 0; ch < NCH; ch++) {
        CP_WAIT1();
        __syncthreads();
        const int buf = ch & 1;
        const uint4* ep = (const uint4*)(smem + (buf ? SM_E1 : SM_E0));
        const float* bp = (const float*)(smem + (buf ? SM_B1 : SM_B0));

        #pragma unroll 2
        for (int c = 0; c < CHUNK; c++) {
            uint4 e0 = ep[c * 4 + 0];
            uint4 e1 = ep[c * 4 + 1];
            uint4 e2 = ep[c * 4 + 2];
            uint4 e3 = ep[c * 4 + 3];
            int a0 = 0, a1 = 0, a2 = 0, a3 = 0;
            a0 = __dp4a((int)xq[0],  (int)e0.x, a0);
            a1 = __dp4a((int)xq[1],  (int)e0.y, a1);
            a2 = __dp4a((int)xq[2],  (int)e0.z, a2);
            a3 = __dp4a((int)xq[3],  (int)e0.w, a3);
            a0 = __dp4a((int)xq[4],  (int)e1.x, a0);
            a1 = __dp4a((int)xq[5],  (int)e1.y, a1);
            a2 = __dp4a((int)xq[6],  (int)e1.z, a2);
            a3 = __dp4a((int)xq[7],  (int)e1.w, a3);
            a0 = __dp4a((int)xq[8],  (int)e2.x, a0);
            a1 = __dp4a((int)xq[9],  (int)e2.y, a1);
            a2 = __dp4a((int)xq[10], (int)e2.z, a2);
            a3 = __dp4a((int)xq[11], (int)e2.w, a3);
            a0 = __dp4a((int)xq[12], (int)e3.x, a0);
            a1 = __dp4a((int)xq[13], (int)e3.y, a1);
            a2 = __dp4a((int)xq[14], (int)e3.z, a2);
            a3 = __dp4a((int)xq[15], (int)e3.w, a3);
            int idot = (a0 + a1) + (a2 + a3);
            float d = fmaf(ns2, (float)idot, bp[c]);
            if (d < lim) {                       // rare (~9 / 1024)
                #pragma unroll
                for (int j = 7; j > 0; j--) { rk[j] = rk[j-1]; rf[j] = rf[j-1]; }
                rk[0] = ch * CHUNK + c; rf[0] = d;
                n_ins = min(n_ins + 1, 8);
                cnt_since++;
                if (d < m1) { m1 = d; lim = d + DELTA; cnt_since = 0; }
            }
        }

        __syncthreads();
        if (ch + 2 < NCH) {
            uint32_t eb = sb + (buf ? SM_E1 : SM_E0);
            uint32_t bb = sb + (buf ? SM_B1 : SM_B0);
            #pragma unroll
            for (int u = 0; u < 4; u++)
                CP_ASYNC16(eb + (tid * 4 + u * BDIM * 4) * 4,
                           g_qe + (ch + 2) * CHUNK * 16 + tid * 4 + u * BDIM * 4);
            if (tid < 32) CP_ASYNC16(bb + tid * 16, g_bsq + (ch + 2) * CHUNK + tid * 4);
        }
        CP_COMMIT();
    }

    // ---- exact resolve over candidates (R1-bitwise arithmetic) ----
    const float* xrow = (const float*)(smem + SM_X) + tid * 65;
    const float4* cb4 = (const float4*)cb;
    int myidx = -1;
    if (cnt_since < 8) {                          // running-min entry still in ring
        float A = 0.0f;
        #pragma unroll
        for (int i = 0; i < D_DIM; i++)
            A = __fadd_rn(A, __fmul_rn(xrow[i], xrow[i]));
        float bestd = 3.402823466e38f; int bestk = 0x7fffffff;
        #pragma unroll
        for (int j = 0; j < 8; j++) {
            if (j < n_ins && rf[j] <= lim) {
                int k = rk[j];
                const float4* er = cb4 + (size_t)k * 16;
                float a0 = 0.f, a1 = 0.f, a2 = 0.f, a3 = 0.f;
                #pragma unroll
                for (int jj = 0; jj < 16; jj++) {
                    float4 ev = er[jj];
                    a0 = fmaf(xrow[4 * jj + 0], ev.x, a0);
                    a1 = fmaf(xrow[4 * jj + 1], ev.y, a1);
                    a2 = fmaf(xrow[4 * jj + 2], ev.z, a2);
                    a3 = fmaf(xrow[4 * jj + 3], ev.w, a3);
                }
                float dot = __fadd_rn(__fadd_rn(a0, a1), __fadd_rn(a2, a3));
                float tv  = __fadd_rn(A, g_bsq[k]);
                float d   = __fadd_rn(tv, -__fmul_rn(2.0f, dot));
                if (d < bestd || (d == bestd && k < bestk)) { bestd = d; bestk = k; }
            }
        }
        myidx = bestk;
    }

    // ---- epilogue ----
    float lsf = 0.0f;
    if (myidx < 0) {
        int pos = atomicAdd(&g_flag_cnt, 1);
        g_flags[pos] = tok;
    } else {
        const int bq = tok >> 11, tq = tok & 2047;
        float* qout = out + ((size_t)bq * D_DIM) * T_LEN + tq;
        const float* er = cb + (size_t)myidx * D_DIM;
        #pragma unroll
        for (int i = 0; i < D_DIM; i++) {
            float xv = xrow[i];
            float dv = __fadd_rn(er[i], -xv);
            lsf = fmaf(dv, dv, lsf);
            qout[(size_t)i * T_LEN] = __fadd_rn(xv, dv);
        }
        out[IDX_OFF + tok] = (float)myidx;
    }
    #pragma unroll
    for (int o = 16; o > 0; o >>= 1)
        lsf += __shfl_down_sync(0xffffffffu, lsf, o);
    if ((tid & 31) == 0) s_wl[tid >> 5] = lsf;
    __syncthreads();
    if (tid == 0) {
        double s = (double)s_wl[0] + (double)s_wl[1] + (double)s_wl[2] + (double)s_wl[3];
        atomicAdd(&g_loss_acc, s);
    }
}

// ---------------- exact fallback (flagged tokens; expected count 0) ----------------
#define EX_GRID 512
__global__ __launch_bounds__(128) void vq_exact_kernel(
    const float* __restrict__ x, const float* __restrict__ cb, float* __restrict__ out)
{
    const int cnt = g_flag_cnt;
    if (blockIdx.x * 8 >= cnt) return;
    __shared__ float sx[8][D_DIM];
    __shared__ int   stok[8];
    const int g = threadIdx.x >> 4, c = threadIdx.x & 15;

    for (int base = blockIdx.x * 8; base < cnt; base += EX_GRID * 8) {
        __syncthreads();
        int slot = base + g;
        if (c == 0) stok[g] = (slot < cnt) ? g_flags[slot] : -1;
        __syncthreads();
        int tok = stok[g];
        if (tok >= 0) {
            #pragma unroll
            for (int i = 0; i < 4; i++) sx[g][c * 4 + i] = x[(size_t)tok * D_DIM + c * 4 + i];
        }
        __syncthreads();

        float best = 3.402823466e38f; int bidx = 0;
        if (tok >= 0) {
            float A = 0.0f;
            #pragma unroll
            for (int i = 0; i < D_DIM; i++) A = __fadd_rn(A, __fmul_rn(sx[g][i], sx[g][i]));
            for (int t = 0; t < K_CODES / 16; t++) {
                int k = c + 16 * t;
                const float* e = cb + (size_t)k * D_DIM;
                float a0 = 0.f, a1 = 0.f, a2 = 0.f, a3 = 0.f;
                #pragma unroll
                for (int j = 0; j < 16; j++) {
                    a0 = fmaf(sx[g][4 * j + 0], e[4 * j + 0], a0);
                    a1 = fmaf(sx[g][4 * j + 1], e[4 * j + 1], a1);
                    a2 = fmaf(sx[g][4 * j + 2], e[4 * j + 2], a2);
                    a3 = fmaf(sx[g][4 * j + 3], e[4 * j + 3], a3);
                }
                float dot = __fadd_rn(__fadd_rn(a0, a1), __fadd_rn(a2, a3));
                float tv  = __fadd_rn(A, g_bsq[k]);
                float d   = __fadd_rn(tv, -__fmul_rn(2.0f, dot));
                if (d < best) { best = d; bidx = k; }
            }
        }
        #pragma unroll
        for (int o = 8; o > 0; o >>= 1) {
            float ob = __shfl_down_sync(0xffffffffu, best, o, 16);
            int   oi = __shfl_down_sync(0xffffffffu, bidx, o, 16);
            if (ob < best || (ob == best && oi < bidx)) { best = ob; bidx = oi; }
        }
        if (tok >= 0 && c == 0) {
            const int bq = tok >> 11, tq = tok & 2047;
            float* qout = out + ((size_t)bq * D_DIM) * T_LEN + tq;
            const float* er = cb + (size_t)bidx * D_DIM;
            double ls = 0.0;
            #pragma unroll
            for (int i = 0; i < D_DIM; i++) {
                float xv = sx[g][i];
                float dv = __fadd_rn(er[i], -xv);
                ls += (double)dv * dv;
                qout[(size_t)i * T_LEN] = __fadd_rn(xv, dv);
            }
            out[IDX_OFF + tok] = (float)bidx;
            atomicAdd(&g_loss_acc, ls);
        }
    }
}

__global__ void vq_finalize_kernel(float* __restrict__ out) {
    double m = g_loss_acc / (double)((size_t)N_TOK * D_DIM);
    out[LOSS_OFF] = (float)(m + 0.25 * m);
}

extern "C" void kernel_launch(void* const* d_in, const int* in_sizes, int n_in,
                              void* d_out, int out_size) {
    const float* x  = (const float*)d_in[0];
    const float* cb = (const float*)d_in[1];
    float* out = (float*)d_out;
    (void)in_sizes; (void)n_in; (void)out_size;

    cudaFuncSetAttribute(vq_screen_kernel, cudaFuncAttributeMaxDynamicSharedMemorySize, SMEM_SZ);

    vq_bsq_init_kernel<<<8, 128>>>(cb);
    vq_quant_x_kernel<<<N_TOK / 256, 256>>>(x);
    vq_quant_e_kernel<<<(K_CODES * 16) / 256, 256>>>(cb);
    vq_screen_kernel<<<N_TOK / BDIM, BDIM, SMEM_SZ>>>(x, cb, out);
    vq_exact_kernel<<<EX_GRID, 128>>>(x, cb, out);
    vq_finalize_kernel<<<1, 1>>>(out);
}